// round 14
// baseline (speedup 1.0000x reference)
#include <cuda_runtime.h>
#include <cuda_bf16.h>
#include <math.h>
#include <stdint.h>

// Problem constants (fixed by reference setup_inputs)
#define T_TOK   8192
#define DIM     1024
#define HEADS   16
#define HD      64
#define SEQ     1024
#define BATCH   8
#define QKV_COLS 3072
#define EPSF 1.1920928955078125e-07f

// Scratch (device globals — no allocation allowed)
__device__ float g_qkv[(size_t)T_TOK * QKV_COLS];               // [T,3,H,D] fp32
__device__ __nv_bfloat16 g_xhi[(size_t)T_TOK * DIM];
__device__ __nv_bfloat16 g_xlo[(size_t)T_TOK * DIM];
__device__ __nv_bfloat16 g_wqhi[(size_t)QKV_COLS * DIM];
__device__ __nv_bfloat16 g_wqlo[(size_t)QKV_COLS * DIM];
__device__ __nv_bfloat16 g_wphi[(size_t)DIM * DIM];
__device__ __nv_bfloat16 g_wplo[(size_t)DIM * DIM];
__device__ __nv_bfloat16 g_ahi[(size_t)T_TOK * DIM];
__device__ __nv_bfloat16 g_alo[(size_t)T_TOK * DIM];
// head-major [B,H,S,D] split q/k/v
#define HSZ ((size_t)BATCH * HEADS * SEQ * HD)
__device__ __nv_bfloat16 g_qh[HSZ], g_ql[HSZ];
__device__ __nv_bfloat16 g_kh[HSZ], g_kl[HSZ];
__device__ __nv_bfloat16 g_vh[HSZ], g_vl[HSZ];

// ===========================================================================
// Common helpers
// ===========================================================================
__device__ __forceinline__ uint32_t smem_u32(const void* p) {
    uint32_t a;
    asm("{ .reg .u64 t; cvta.to.shared.u64 t, %1; cvt.u32.u64 %0, t; }"
        : "=r"(a) : "l"(p));
    return a;
}
__device__ __forceinline__ void cpa16(uint32_t s, const void* g) {
    asm volatile("cp.async.cg.shared.global [%0], [%1], 16;" :: "r"(s), "l"(g));
}
__device__ __forceinline__ void mma_bf16(float* d, const uint32_t* a,
                                         const uint32_t* b) {
    asm volatile(
        "mma.sync.aligned.m16n8k16.row.col.f32.bf16.bf16.f32 "
        "{%0,%1,%2,%3}, {%4,%5,%6,%7}, {%8,%9}, {%0,%1,%2,%3};"
        : "+f"(d[0]), "+f"(d[1]), "+f"(d[2]), "+f"(d[3])
        : "r"(a[0]), "r"(a[1]), "r"(a[2]), "r"(a[3]), "r"(b[0]), "r"(b[1]));
}
__device__ __forceinline__ void ldsm4(uint32_t* r, uint32_t a) {
    asm volatile("ldmatrix.sync.aligned.m8n8.x4.shared.b16 {%0,%1,%2,%3}, [%4];"
        : "=r"(r[0]), "=r"(r[1]), "=r"(r[2]), "=r"(r[3]) : "r"(a));
}
__device__ __forceinline__ void ldsm4t(uint32_t* r, uint32_t a) {
    asm volatile("ldmatrix.sync.aligned.m8n8.x4.trans.shared.b16 {%0,%1,%2,%3}, [%4];"
        : "=r"(r[0]), "=r"(r[1]), "=r"(r[2]), "=r"(r[3]) : "r"(a));
}
__device__ __forceinline__ float ex2(float x) {
    float r; asm("ex2.approx.f32 %0, %1;" : "=f"(r) : "f"(x)); return r;
}
__device__ __forceinline__ uint32_t packbf(float lo, float hi) {
    uint32_t r;
    asm("cvt.rn.bf16x2.f32 %0, %1, %2;" : "=r"(r) : "f"(hi), "f"(lo));
    return r;
}
__device__ __forceinline__ float bfhi(float x) {
    return __bfloat162float(__float2bfloat16_rn(x));
}

// ===========================================================================
// fp32 -> (hi, lo) bf16 split
// ===========================================================================
__global__ __launch_bounds__(256) void split_kernel(
    const float* __restrict__ src, __nv_bfloat16* __restrict__ hi,
    __nv_bfloat16* __restrict__ lo, int n4)
{
    const int i = blockIdx.x * 256 + threadIdx.x;
    if (i >= n4) return;
    const float4 v = ((const float4*)src)[i];
    float h0 = bfhi(v.x), h1 = bfhi(v.y), h2 = bfhi(v.z), h3 = bfhi(v.w);
    uint32_t* hp = (uint32_t*)(hi) + i * 2;
    hp[0] = packbf(h0, h1);
    hp[1] = packbf(h2, h3);
    uint32_t* lp = (uint32_t*)(lo) + i * 2;
    lp[0] = packbf(v.x - h0, v.y - h1);
    lp[1] = packbf(v.z - h2, v.w - h3);
}

// ===========================================================================
// Split-bf16 GEMM — 6-stage ring, TWO BK=32 chunks per barrier (16 barriers).
// Single barrier per iteration: iter i computes chunks 2i,2i+1 and tail-loads
// chunks 2i+4,2i+5 into the stages consumed at iter i-1 (fenced by the
// top-of-iter barrier). smem 216KB -> 1 CTA/SM.
// ===========================================================================
#define SROWB 144
#define REG_B 18432
#define STAGEB 36864
#define GSMEM (6 * STAGEB)               // 221184

__global__ __launch_bounds__(256, 1) void gemm_split_kernel(
    const __nv_bfloat16* __restrict__ Ahi, const __nv_bfloat16* __restrict__ Alo,
    const __nv_bfloat16* __restrict__ Bhi, const __nv_bfloat16* __restrict__ Blo,
    float* __restrict__ C, int Nstride)
{
    extern __shared__ char smc[];
    const int tid = threadIdx.x, wid = tid >> 5, lane = tid & 31;
    const int bm = blockIdx.y * 128, bn = blockIdx.x * 128;
    const int wm = (wid >> 2) * 64;
    const int wn = (wid & 3) * 32;
    const int lr = lane >> 2, lc = lane & 3;
    const uint32_t sb0 = smem_u32(smc);
    const uint32_t ga_off =
        (uint32_t)((lane & 7) + ((lane >> 3) & 1) * 8) * SROWB +
        ((lane >> 4) & 1) * 16;
    const uint32_t gb_off =
        (uint32_t)((lane & 7) + ((lane >> 4) & 1) * 8) * SROWB +
        ((lane >> 3) & 1) * 16;

    float acc[4][4][4];
#pragma unroll
    for (int i = 0; i < 4; ++i)
#pragma unroll
        for (int j = 0; j < 4; ++j)
#pragma unroll
            for (int r = 0; r < 4; ++r) acc[i][j][r] = 0.f;

    // load ONE chunk into its stage (no commit)
    auto load_chunk = [&](int chunk) {
        char* base = smc + (chunk % 6) * STAGEB;
        const int k0 = chunk * 32;
#pragma unroll
        for (int g = 0; g < 2; ++g) {
            const int idx = tid + g * 256;
            const int row = idx >> 2, cc = idx & 3;
            const uint32_t so = (uint32_t)(row * SROWB + cc * 16);
            const size_t ga = (size_t)(bm + row) * 1024 + k0 + cc * 8;
            const size_t gb = (size_t)(bn + row) * 1024 + k0 + cc * 8;
            cpa16(smem_u32(base + so), Ahi + ga);
            cpa16(smem_u32(base + 64 + so), Alo + ga);
            cpa16(smem_u32(base + REG_B + so), Bhi + gb);
            cpa16(smem_u32(base + REG_B + 64 + so), Blo + gb);
        }
    };
    // load a PAIR of chunks as one commit group
    auto load_pair = [&](int j) {          // chunks 2j, 2j+1
        load_chunk(2 * j);
        load_chunk(2 * j + 1);
        asm volatile("cp.async.commit_group;" ::: "memory");
    };

    auto compute = [&](int S) {
        const uint32_t sbase = sb0 + (uint32_t)S * STAGEB;
#pragma unroll
        for (int ks = 0; ks < 2; ++ks) {
            uint32_t bh[2][4], bl[2][4];
#pragma unroll
            for (int np = 0; np < 2; ++np) {
                const uint32_t bb = sbase + REG_B + (wn + np * 16) * SROWB
                                    + gb_off + ks * 32;
                ldsm4(bh[np], bb);
                ldsm4(bl[np], bb + 64);
            }
            uint32_t aa[2][8];
            {
                const uint32_t ab0 = sbase + wm * SROWB + ga_off + ks * 32;
                ldsm4(aa[0], ab0);
                ldsm4(aa[0] + 4, ab0 + 64);
            }
#pragma unroll
            for (int mf = 0; mf < 4; ++mf) {
                const int cur = mf & 1;
                if (mf < 3) {
                    const uint32_t abn = sbase + (wm + (mf + 1) * 16) * SROWB
                                         + ga_off + ks * 32;
                    ldsm4(aa[cur ^ 1], abn);
                    ldsm4(aa[cur ^ 1] + 4, abn + 64);
                }
                const uint32_t* ah = aa[cur];
                const uint32_t* al = aa[cur] + 4;
#pragma unroll
                for (int nf = 0; nf < 4; ++nf)
                    mma_bf16(acc[mf][nf], ah, bh[nf >> 1] + (nf & 1) * 2);
#pragma unroll
                for (int nf = 0; nf < 4; ++nf)
                    mma_bf16(acc[mf][nf], ah, bl[nf >> 1] + (nf & 1) * 2);
#pragma unroll
                for (int nf = 0; nf < 4; ++nf)
                    mma_bf16(acc[mf][nf], al, bh[nf >> 1] + (nf & 1) * 2);
            }
        }
    };

    load_pair(0);   // chunks 0,1 -> stages 0,1
    load_pair(1);   // chunks 2,3 -> stages 2,3

    for (int i = 0; i < 16; ++i) {
        if (i < 15) { asm volatile("cp.async.wait_group 1;" ::: "memory"); }
        else        { asm volatile("cp.async.wait_group 0;" ::: "memory"); }
        __syncthreads();   // chunks 2i,2i+1 visible; stages of iter i-1 free

        compute((2 * i) % 6);
        compute((2 * i + 1) % 6);

        if (i + 2 < 16) load_pair(i + 2);   // -> stages freed by iter i-1
    }

#pragma unroll
    for (int mf = 0; mf < 4; ++mf) {
        const int r0 = bm + wm + mf * 16 + lr;
#pragma unroll
        for (int nf = 0; nf < 4; ++nf) {
            const int col = bn + wn + nf * 8 + lc * 2;
            *(float2*)(C + (size_t)r0 * Nstride + col) =
                make_float2(acc[mf][nf][0], acc[mf][nf][1]);
            *(float2*)(C + (size_t)(r0 + 8) * Nstride + col) =
                make_float2(acc[mf][nf][2], acc[mf][nf][3]);
        }
    }
}

// ---------------------------------------------------------------------------
// Fused RMSNorm + RoPE + head-major split (coalesced stores).
// ---------------------------------------------------------------------------
__global__ __launch_bounds__(256) void rmsrope_kernel(
    const float* __restrict__ qkv,
    const float* __restrict__ rope_cos, const float* __restrict__ rope_sin,
    const float* __restrict__ qw, const float* __restrict__ kw,
    __nv_bfloat16* __restrict__ qh, __nv_bfloat16* __restrict__ ql,
    __nv_bfloat16* __restrict__ kh, __nv_bfloat16* __restrict__ kl,
    __nv_bfloat16* __restrict__ vh, __nv_bfloat16* __restrict__ vl)
{
    const int t = blockIdx.x;
    const int warp = threadIdx.x >> 5, lane = threadIdx.x & 31;
    const int bb = t >> 10, ss = t & 1023;
    const float c1 = rope_cos[(size_t)t * HD + lane];
    const float c2 = rope_cos[(size_t)t * HD + 32 + lane];
    const float s1 = rope_sin[(size_t)t * HD + lane];
    const float s2 = rope_sin[(size_t)t * HD + 32 + lane];
    const float qscale = 0.125f * 1.4426950408889634f;
    const int m2 = (lane & 15) * 2;
    const bool hiHalf = lane >= 16;

    auto store_pair = [&](float r1, float r2, __nv_bfloat16* dh,
                          __nv_bfloat16* dl, size_t dst) {
        const float a1 = __shfl_sync(0xffffffffu, r1, m2);
        const float b1 = __shfl_sync(0xffffffffu, r1, m2 + 1);
        const float a2 = __shfl_sync(0xffffffffu, r2, m2);
        const float b2 = __shfl_sync(0xffffffffu, r2, m2 + 1);
        const float a = hiHalf ? a2 : a1;
        const float b = hiHalf ? b2 : b1;
        const float ha = bfhi(a), hb = bfhi(b);
        ((uint32_t*)(dh + dst))[lane] = packbf(ha, hb);
        ((uint32_t*)(dl + dst))[lane] = packbf(a - ha, b - hb);
    };

#pragma unroll
    for (int hh = 0; hh < 2; ++hh) {
        const int h = warp * 2 + hh;
        const size_t dst = ((size_t)(bb * HEADS + h) * SEQ + ss) * HD;
#pragma unroll
        for (int qk = 0; qk < 2; ++qk) {
            const float* p = qkv + (size_t)t * QKV_COLS + qk * DIM + h * HD;
            float x1 = p[lane], x2 = p[lane + 32];
            float sq = x1 * x1 + x2 * x2;
#pragma unroll
            for (int off = 16; off; off >>= 1)
                sq += __shfl_xor_sync(0xffffffffu, sq, off);
            const float r = rsqrtf(sq * (1.f / 64.f) + EPSF);
            const float* w = qk ? kw : qw;
            const float n1 = x1 * r * w[lane];
            const float n2 = x2 * r * w[lane + 32];
            float r1 = n1 * c1 - n2 * s1;
            float r2 = n2 * c2 + n1 * s2;
            if (qk == 0) { r1 *= qscale; r2 *= qscale; }
            store_pair(r1, r2, qk ? kh : qh, qk ? kl : ql, dst);
        }
        const float* pv = qkv + (size_t)t * QKV_COLS + 2 * DIM + h * HD;
        store_pair(pv[lane], pv[lane + 32], vh, vl, dst);
    }
}

// ===========================================================================
// Flash attention — unchanged from R13 (measured best): 128-key blocks,
// 3-stage ring, single barrier per block, tail-load after compute.
// ===========================================================================
#define KROWB 272
#define KTILE 34816                      // 128 rows * 272
#define KSTG  69632                      // K + V
#define ATT_SMEM (3 * KSTG)              // 208896

__global__ __launch_bounds__(256, 1) void attn_kernel(
    const __nv_bfloat16* __restrict__ qh, const __nv_bfloat16* __restrict__ ql,
    const __nv_bfloat16* __restrict__ kh, const __nv_bfloat16* __restrict__ kl,
    const __nv_bfloat16* __restrict__ vh, const __nv_bfloat16* __restrict__ vl,
    __nv_bfloat16* __restrict__ ohi, __nv_bfloat16* __restrict__ olo)
{
    extern __shared__ char sma[];
    const uint32_t sb = smem_u32(sma);
    const int tid = threadIdx.x, wid = tid >> 5, lane = tid & 31;
    const int lr = lane >> 2, lc = lane & 3;
    const int h = blockIdx.y, b = blockIdx.z;
    const int q0 = blockIdx.x * 128;
    const int wq = wid * 16;
    const size_t hb = (size_t)(b * HEADS + h) * SEQ * HD;

    // --- Q tile load (into stage-0 region; extracted before load_kv(0)) ---
#pragma unroll
    for (int i = 0; i < 8; ++i) {
        const int slot = tid + i * 256;
        const int row = slot >> 4, c = slot & 15;
        const __nv_bfloat16* src = (c < 8 ? qh : ql) + hb + (size_t)(q0 + row) * HD + (c & 7) * 8;
        cpa16(sb + row * KROWB + c * 16, src);
    }
    asm volatile("cp.async.commit_group;" ::: "memory");
    asm volatile("cp.async.wait_group 0;" ::: "memory");
    __syncthreads();

    const uint32_t a_off =
        (uint32_t)((lane & 7) + ((lane >> 3) & 1) * 8) * KROWB + ((lane >> 4) & 1) * 16;
    const uint32_t b_off =
        (uint32_t)((lane & 7) + ((lane >> 4) & 1) * 8) * KROWB + ((lane >> 3) & 1) * 16;
    const uint32_t v_off =
        (uint32_t)(lane & 15) * KROWB + ((lane >> 4) & 1) * 16;
    uint32_t qfh[4][4], qfl[4][4];
#pragma unroll
    for (int ks = 0; ks < 4; ++ks) {
        ldsm4(qfh[ks], sb + wq * KROWB + a_off + ks * 32);
        ldsm4(qfl[ks], sb + wq * KROWB + a_off + ks * 32 + 128);
    }
    __syncthreads();   // Q region free for K/V stages

    auto load_kv = [&](int kb, int s) {
        const uint32_t kst = sb + s * KSTG;
#pragma unroll
        for (int i = 0; i < 8; ++i) {
            const int slot = tid + i * 256;
            const int row = slot >> 4, c = slot & 15;
            const size_t g = hb + (size_t)(kb * 128 + row) * HD + (c & 7) * 8;
            cpa16(kst + row * KROWB + c * 16, (c < 8 ? kh : kl) + g);
        }
#pragma unroll
        for (int i = 0; i < 8; ++i) {
            const int slot = tid + i * 256;
            const int row = slot >> 4, c = slot & 15;
            const size_t g = hb + (size_t)(kb * 128 + row) * HD + (c & 7) * 8;
            cpa16(kst + KTILE + row * KROWB + c * 16, (c < 8 ? vh : vl) + g);
        }
        asm volatile("cp.async.commit_group;" ::: "memory");
    };

    load_kv(0, 0);
    load_kv(1, 1);

    float m0 = -1e30f, m1 = -1e30f, l0 = 0.f, l1 = 0.f;
    float o[8][4];
#pragma unroll
    for (int nf = 0; nf < 8; ++nf)
#pragma unroll
        for (int r = 0; r < 4; ++r) o[nf][r] = 0.f;

    for (int kb = 0; kb < 8; ++kb) {
        const uint32_t kbase = sb + (kb % 3) * KSTG;
        const uint32_t vbase = kbase + KTILE;
        if (kb < 7) { asm volatile("cp.async.wait_group 1;" ::: "memory"); }
        else        { asm volatile("cp.async.wait_group 0;" ::: "memory"); }
        __syncthreads();   // stage kb visible; stage (kb-1)%3 free

        // --- S = Q K^T (3-term), 128 keys ---
        float s[16][4];
#pragma unroll
        for (int nf = 0; nf < 16; ++nf)
#pragma unroll
            for (int r = 0; r < 4; ++r) s[nf][r] = 0.f;

#pragma unroll
        for (int it = 0; it < 32; ++it) {
            const int ks = it >> 3, np = it & 7;
            uint32_t bh[4], bl[4];
            const uint32_t ba = kbase + np * 16 * KROWB + b_off + ks * 32;
            ldsm4(bh, ba);
            ldsm4(bl, ba + 128);
            mma_bf16(s[2 * np],     qfh[ks], bh);
            mma_bf16(s[2 * np + 1], qfh[ks], bh + 2);
            mma_bf16(s[2 * np],     qfh[ks], bl);
            mma_bf16(s[2 * np + 1], qfh[ks], bl + 2);
            mma_bf16(s[2 * np],     qfl[ks], bh);
            mma_bf16(s[2 * np + 1], qfl[ks], bh + 2);
        }

        // --- online softmax (rows lr, lr+8) ---
        float mx0 = -1e30f, mx1 = -1e30f;
#pragma unroll
        for (int nf = 0; nf < 16; ++nf) {
            mx0 = fmaxf(mx0, fmaxf(s[nf][0], s[nf][1]));
            mx1 = fmaxf(mx1, fmaxf(s[nf][2], s[nf][3]));
        }
        mx0 = fmaxf(mx0, __shfl_xor_sync(0xffffffffu, mx0, 1));
        mx0 = fmaxf(mx0, __shfl_xor_sync(0xffffffffu, mx0, 2));
        mx1 = fmaxf(mx1, __shfl_xor_sync(0xffffffffu, mx1, 1));
        mx1 = fmaxf(mx1, __shfl_xor_sync(0xffffffffu, mx1, 2));
        const float nm0 = fmaxf(m0, mx0), nm1 = fmaxf(m1, mx1);
        const float cr0 = ex2(m0 - nm0), cr1 = ex2(m1 - nm1);
        m0 = nm0; m1 = nm1;
        float sum0 = 0.f, sum1 = 0.f;
#pragma unroll
        for (int nf = 0; nf < 16; ++nf) {
            s[nf][0] = ex2(s[nf][0] - nm0); sum0 += s[nf][0];
            s[nf][1] = ex2(s[nf][1] - nm0); sum0 += s[nf][1];
            s[nf][2] = ex2(s[nf][2] - nm1); sum1 += s[nf][2];
            s[nf][3] = ex2(s[nf][3] - nm1); sum1 += s[nf][3];
        }
        sum0 += __shfl_xor_sync(0xffffffffu, sum0, 1);
        sum0 += __shfl_xor_sync(0xffffffffu, sum0, 2);
        sum1 += __shfl_xor_sync(0xffffffffu, sum1, 1);
        sum1 += __shfl_xor_sync(0xffffffffu, sum1, 2);
        l0 = l0 * cr0 + sum0;
        l1 = l1 * cr1 + sum1;
#pragma unroll
        for (int nf = 0; nf < 8; ++nf) {
            o[nf][0] *= cr0; o[nf][1] *= cr0;
            o[nf][2] *= cr1; o[nf][3] *= cr1;
        }

        // --- pack P hi/lo (8 k-steps of 16 keys) ---
        uint32_t ph[8][4], pl[8][4];
#pragma unroll
        for (int ks = 0; ks < 8; ++ks) {
            const float p00 = s[2 * ks][0],     p01 = s[2 * ks][1];
            const float p10 = s[2 * ks][2],     p11 = s[2 * ks][3];
            const float p20 = s[2 * ks + 1][0], p21 = s[2 * ks + 1][1];
            const float p30 = s[2 * ks + 1][2], p31 = s[2 * ks + 1][3];
            const float h00 = bfhi(p00), h01 = bfhi(p01);
            const float h10 = bfhi(p10), h11 = bfhi(p11);
            const float h20 = bfhi(p20), h21 = bfhi(p21);
            const float h30 = bfhi(p30), h31 = bfhi(p31);
            ph[ks][0] = packbf(h00, h01); pl[ks][0] = packbf(p00 - h00, p01 - h01);
            ph[ks][1] = packbf(h10, h11); pl[ks][1] = packbf(p10 - h10, p11 - h11);
            ph[ks][2] = packbf(h20, h21); pl[ks][2] = packbf(p20 - h20, p21 - h21);
            ph[ks][3] = packbf(h30, h31); pl[ks][3] = packbf(p30 - h30, p31 - h31);
        }

        // --- O += P V (3-term) ---
#pragma unroll
        for (int it = 0; it < 32; ++it) {
            const int ks = it >> 2, ng = it & 3;
            uint32_t vfh[4], vfl[4];
            const uint32_t va = vbase + ks * 16 * KROWB + v_off + ng * 32;
            ldsm4t(vfh, va);
            ldsm4t(vfl, va + 128);
            mma_bf16(o[2 * ng],     ph[ks], vfh);
            mma_bf16(o[2 * ng + 1], ph[ks], vfh + 2);
            mma_bf16(o[2 * ng],     ph[ks], vfl);
            mma_bf16(o[2 * ng + 1], ph[ks], vfl + 2);
            mma_bf16(o[2 * ng],     pl[ks], vfh);
            mma_bf16(o[2 * ng + 1], pl[ks], vfh + 2);
        }

        // tail-load AFTER compute (R11-proven ordering)
        if (kb + 2 < 8) load_kv(kb + 2, (kb + 2) % 3);
    }

    // --- epilogue ---
    const float i0 = 1.f / l0, i1 = 1.f / l1;
    const int t0 = b * SEQ + q0 + wq + lr;
#pragma unroll
    for (int nf = 0; nf < 8; ++nf) {
        const int col = h * HD + nf * 8 + lc * 2;
        const float v0 = o[nf][0] * i0, v1 = o[nf][1] * i0;
        const float h0 = bfhi(v0), h1 = bfhi(v1);
        ((uint32_t*)ohi)[((size_t)t0 * DIM + col) >> 1] = packbf(h0, h1);
        ((uint32_t*)olo)[((size_t)t0 * DIM + col) >> 1] = packbf(v0 - h0, v1 - h1);
        const float v2 = o[nf][2] * i1, v3 = o[nf][3] * i1;
        const float h2 = bfhi(v2), h3 = bfhi(v3);
        ((uint32_t*)ohi)[((size_t)(t0 + 8) * DIM + col) >> 1] = packbf(h2, h3);
        ((uint32_t*)olo)[((size_t)(t0 + 8) * DIM + col) >> 1] = packbf(v2 - h2, v3 - h3);
    }
}

// ---------------------------------------------------------------------------
extern "C" void kernel_launch(void* const* d_in, const int* in_sizes, int n_in,
                              void* d_out, int out_size)
{
    const float *x = 0, *rc = 0, *rs = 0, *wqkv = 0, *wproj = 0, *qw = 0, *kw = 0;
    for (int i = 0; i < n_in; ++i) {
        const int s = in_sizes[i];
        if (s == T_TOK * DIM && !x)            x = (const float*)d_in[i];
        else if (s == T_TOK * HD)              { if (!rc) rc = (const float*)d_in[i];
                                                 else if (!rs) rs = (const float*)d_in[i]; }
        else if (s == QKV_COLS * DIM)          wqkv = (const float*)d_in[i];
        else if (s == DIM * DIM && !wproj)     wproj = (const float*)d_in[i];
        else if (s == HD)                      { if (!qw) qw = (const float*)d_in[i];
                                                 else if (!kw) kw = (const float*)d_in[i]; }
    }
    float* out = (float*)d_out;

    void *pqkv, *pxh, *pxl, *pwqh, *pwql, *pwph, *pwpl, *pah, *pal;
    void *pqh, *pql, *pkh, *pkl, *pvh, *pvl;
    cudaGetSymbolAddress(&pqkv, g_qkv);
    cudaGetSymbolAddress(&pxh, g_xhi);  cudaGetSymbolAddress(&pxl, g_xlo);
    cudaGetSymbolAddress(&pwqh, g_wqhi); cudaGetSymbolAddress(&pwql, g_wqlo);
    cudaGetSymbolAddress(&pwph, g_wphi); cudaGetSymbolAddress(&pwpl, g_wplo);
    cudaGetSymbolAddress(&pah, g_ahi);  cudaGetSymbolAddress(&pal, g_alo);
    cudaGetSymbolAddress(&pqh, g_qh);   cudaGetSymbolAddress(&pql, g_ql);
    cudaGetSymbolAddress(&pkh, g_kh);   cudaGetSymbolAddress(&pkl, g_kl);
    cudaGetSymbolAddress(&pvh, g_vh);   cudaGetSymbolAddress(&pvl, g_vl);

    cudaFuncSetAttribute(gemm_split_kernel,
                         cudaFuncAttributeMaxDynamicSharedMemorySize, GSMEM);
    cudaFuncSetAttribute(attn_kernel,
                         cudaFuncAttributeMaxDynamicSharedMemorySize, ATT_SMEM);

    // 0) fp32 -> (hi,lo) bf16 splits
    split_kernel<<<(T_TOK * DIM / 4 + 255) / 256, 256>>>(
        x, (__nv_bfloat16*)pxh, (__nv_bfloat16*)pxl, T_TOK * DIM / 4);
    split_kernel<<<(QKV_COLS * DIM / 4 + 255) / 256, 256>>>(
        wqkv, (__nv_bfloat16*)pwqh, (__nv_bfloat16*)pwql, QKV_COLS * DIM / 4);
    split_kernel<<<(DIM * DIM / 4 + 255) / 256, 256>>>(
        wproj, (__nv_bfloat16*)pwph, (__nv_bfloat16*)pwpl, DIM * DIM / 4);

    // 1) QKV = x @ w_qkv^T
    gemm_split_kernel<<<dim3(QKV_COLS / 128, T_TOK / 128), 256, GSMEM>>>(
        (__nv_bfloat16*)pxh, (__nv_bfloat16*)pxl,
        (__nv_bfloat16*)pwqh, (__nv_bfloat16*)pwql, (float*)pqkv, QKV_COLS);
    // 2) RMSNorm + RoPE + split q,k,v to head-major bf16
    rmsrope_kernel<<<T_TOK, 256>>>(
        (const float*)pqkv, rc, rs, qw, kw,
        (__nv_bfloat16*)pqh, (__nv_bfloat16*)pql,
        (__nv_bfloat16*)pkh, (__nv_bfloat16*)pkl,
        (__nv_bfloat16*)pvh, (__nv_bfloat16*)pvl);
    // 3) Attention
    attn_kernel<<<dim3(SEQ / 128, HEADS, BATCH), 256, ATT_SMEM>>>(
        (__nv_bfloat16*)pqh, (__nv_bfloat16*)pql,
        (__nv_bfloat16*)pkh, (__nv_bfloat16*)pkl,
        (__nv_bfloat16*)pvh, (__nv_bfloat16*)pvl,
        (__nv_bfloat16*)pah, (__nv_bfloat16*)pal);
    // 4) out = attn @ w_proj^T
    gemm_split_kernel<<<dim3(DIM / 128, T_TOK / 128), 256, GSMEM>>>(
        (__nv_bfloat16*)pah, (__nv_bfloat16*)pal,
        (__nv_bfloat16*)pwph, (__nv_bfloat16*)pwpl, out, DIM);
}

// round 15
// speedup vs baseline: 1.1022x; 1.1022x over previous
#include <cuda_runtime.h>
#include <cuda_bf16.h>
#include <math.h>
#include <stdint.h>

// Problem constants (fixed by reference setup_inputs)
#define T_TOK   8192
#define DIM     1024
#define HEADS   16
#define HD      64
#define SEQ     1024
#define BATCH   8
#define QKV_COLS 3072
#define EPSF 1.1920928955078125e-07f

// Scratch (device globals — no allocation allowed)
__device__ float g_qkv[(size_t)T_TOK * QKV_COLS];               // [T,3,H,D] fp32
__device__ __nv_bfloat16 g_xhi[(size_t)T_TOK * DIM];
__device__ __nv_bfloat16 g_xlo[(size_t)T_TOK * DIM];
__device__ __nv_bfloat16 g_wqhi[(size_t)QKV_COLS * DIM];
__device__ __nv_bfloat16 g_wqlo[(size_t)QKV_COLS * DIM];
__device__ __nv_bfloat16 g_wphi[(size_t)DIM * DIM];
__device__ __nv_bfloat16 g_wplo[(size_t)DIM * DIM];
__device__ __nv_bfloat16 g_ahi[(size_t)T_TOK * DIM];
__device__ __nv_bfloat16 g_alo[(size_t)T_TOK * DIM];
// head-major [B,H,S,D] split q/k/v
#define HSZ ((size_t)BATCH * HEADS * SEQ * HD)
__device__ __nv_bfloat16 g_qh[HSZ], g_ql[HSZ];
__device__ __nv_bfloat16 g_kh[HSZ], g_kl[HSZ];
__device__ __nv_bfloat16 g_vh[HSZ], g_vl[HSZ];

// ===========================================================================
// Common helpers
// ===========================================================================
__device__ __forceinline__ uint32_t smem_u32(const void* p) {
    uint32_t a;
    asm("{ .reg .u64 t; cvta.to.shared.u64 t, %1; cvt.u32.u64 %0, t; }"
        : "=r"(a) : "l"(p));
    return a;
}
__device__ __forceinline__ void cpa16(uint32_t s, const void* g) {
    asm volatile("cp.async.cg.shared.global [%0], [%1], 16;" :: "r"(s), "l"(g));
}
__device__ __forceinline__ void mma_bf16(float* d, const uint32_t* a,
                                         const uint32_t* b) {
    asm volatile(
        "mma.sync.aligned.m16n8k16.row.col.f32.bf16.bf16.f32 "
        "{%0,%1,%2,%3}, {%4,%5,%6,%7}, {%8,%9}, {%0,%1,%2,%3};"
        : "+f"(d[0]), "+f"(d[1]), "+f"(d[2]), "+f"(d[3])
        : "r"(a[0]), "r"(a[1]), "r"(a[2]), "r"(a[3]), "r"(b[0]), "r"(b[1]));
}
__device__ __forceinline__ void ldsm4(uint32_t* r, uint32_t a) {
    asm volatile("ldmatrix.sync.aligned.m8n8.x4.shared.b16 {%0,%1,%2,%3}, [%4];"
        : "=r"(r[0]), "=r"(r[1]), "=r"(r[2]), "=r"(r[3]) : "r"(a));
}
__device__ __forceinline__ void ldsm4t(uint32_t* r, uint32_t a) {
    asm volatile("ldmatrix.sync.aligned.m8n8.x4.trans.shared.b16 {%0,%1,%2,%3}, [%4];"
        : "=r"(r[0]), "=r"(r[1]), "=r"(r[2]), "=r"(r[3]) : "r"(a));
}
__device__ __forceinline__ float ex2(float x) {
    float r; asm("ex2.approx.f32 %0, %1;" : "=f"(r) : "f"(x)); return r;
}
__device__ __forceinline__ uint32_t packbf(float lo, float hi) {
    uint32_t r;
    asm("cvt.rn.bf16x2.f32 %0, %1, %2;" : "=r"(r) : "f"(hi), "f"(lo));
    return r;
}
__device__ __forceinline__ float bfhi(float x) {
    return __bfloat162float(__float2bfloat16_rn(x));
}

// ===========================================================================
// Merged fp32 -> (hi, lo) bf16 split for x, w_qkv, w_proj in ONE launch.
// Segment boundaries in float4 units.
// ===========================================================================
#define N4_X   (T_TOK * DIM / 4)          // 2097152
#define N4_WQ  (QKV_COLS * DIM / 4)       // 786432
#define N4_WP  (DIM * DIM / 4)            // 262144
#define N4_TOT (N4_X + N4_WQ + N4_WP)     // 3145728

__global__ __launch_bounds__(256) void split_all_kernel(
    const float* __restrict__ x, const float* __restrict__ wq,
    const float* __restrict__ wp,
    __nv_bfloat16* __restrict__ xh, __nv_bfloat16* __restrict__ xl,
    __nv_bfloat16* __restrict__ wqh, __nv_bfloat16* __restrict__ wql,
    __nv_bfloat16* __restrict__ wph, __nv_bfloat16* __restrict__ wpl)
{
    int i = blockIdx.x * 256 + threadIdx.x;
    if (i >= N4_TOT) return;
    const float* src;
    __nv_bfloat16 *hi, *lo;
    if (i < N4_X)              { src = x;  hi = xh;  lo = xl; }
    else if (i < N4_X + N4_WQ) { i -= N4_X; src = wq; hi = wqh; lo = wql; }
    else                       { i -= N4_X + N4_WQ; src = wp; hi = wph; lo = wpl; }
    const float4 v = ((const float4*)src)[i];
    const float h0 = bfhi(v.x), h1 = bfhi(v.y), h2 = bfhi(v.z), h3 = bfhi(v.w);
    uint32_t* hp = (uint32_t*)(hi) + (size_t)i * 2;
    hp[0] = packbf(h0, h1);
    hp[1] = packbf(h2, h3);
    uint32_t* lp = (uint32_t*)(lo) + (size_t)i * 2;
    lp[0] = packbf(v.x - h0, v.y - h1);
    lp[1] = packbf(v.z - h2, v.w - h3);
}

// ===========================================================================
// Split-bf16 GEMM — EXACT R13 structure (measured best: 419.6us, tensor 69.9%).
// 2 CTAs/SM, single-barrier 3-stage mainloop, tail-load AFTER compute.
// ===========================================================================
#define SROWB 144
#define REG_B 18432
#define STAGEB 36864
#define GSMEM (3 * STAGEB)               // 110592 -> 2 CTAs/SM

__global__ __launch_bounds__(256, 2) void gemm_split_kernel(
    const __nv_bfloat16* __restrict__ Ahi, const __nv_bfloat16* __restrict__ Alo,
    const __nv_bfloat16* __restrict__ Bhi, const __nv_bfloat16* __restrict__ Blo,
    float* __restrict__ C, int Nstride)
{
    extern __shared__ char smc[];
    const int tid = threadIdx.x, wid = tid >> 5, lane = tid & 31;
    const int bm = blockIdx.y * 128, bn = blockIdx.x * 128;
    const int wm = (wid >> 2) * 64;
    const int wn = (wid & 3) * 32;
    const int lr = lane >> 2, lc = lane & 3;
    const uint32_t sb0 = smem_u32(smc);
    const uint32_t ga_off =
        (uint32_t)((lane & 7) + ((lane >> 3) & 1) * 8) * SROWB +
        ((lane >> 4) & 1) * 16;
    const uint32_t gb_off =
        (uint32_t)((lane & 7) + ((lane >> 4) & 1) * 8) * SROWB +
        ((lane >> 3) & 1) * 16;

    float acc[4][4][4];
#pragma unroll
    for (int i = 0; i < 4; ++i)
#pragma unroll
        for (int j = 0; j < 4; ++j)
#pragma unroll
            for (int r = 0; r < 4; ++r) acc[i][j][r] = 0.f;

    auto load_stage = [&](int s, int chunk) {
        char* base = smc + s * STAGEB;
        const int k0 = chunk * 32;
#pragma unroll
        for (int g = 0; g < 2; ++g) {
            const int idx = tid + g * 256;
            const int row = idx >> 2, cc = idx & 3;
            const uint32_t so = (uint32_t)(row * SROWB + cc * 16);
            const size_t ga = (size_t)(bm + row) * 1024 + k0 + cc * 8;
            const size_t gb = (size_t)(bn + row) * 1024 + k0 + cc * 8;
            cpa16(smem_u32(base + so), Ahi + ga);
            cpa16(smem_u32(base + 64 + so), Alo + ga);
            cpa16(smem_u32(base + REG_B + so), Bhi + gb);
            cpa16(smem_u32(base + REG_B + 64 + so), Blo + gb);
        }
        asm volatile("cp.async.commit_group;" ::: "memory");
    };

    load_stage(0, 0);
    load_stage(1, 1);

    for (int c = 0; c < 32; ++c) {
        if (c < 31) { asm volatile("cp.async.wait_group 1;" ::: "memory"); }
        else        { asm volatile("cp.async.wait_group 0;" ::: "memory"); }
        __syncthreads();

        const uint32_t sbase = sb0 + (c % 3) * STAGEB;
#pragma unroll
        for (int ks = 0; ks < 2; ++ks) {
            uint32_t bh[2][4], bl[2][4];
#pragma unroll
            for (int np = 0; np < 2; ++np) {
                const uint32_t bb = sbase + REG_B + (wn + np * 16) * SROWB
                                    + gb_off + ks * 32;
                ldsm4(bh[np], bb);
                ldsm4(bl[np], bb + 64);
            }
            uint32_t aa[2][8];
            {
                const uint32_t ab0 = sbase + wm * SROWB + ga_off + ks * 32;
                ldsm4(aa[0], ab0);
                ldsm4(aa[0] + 4, ab0 + 64);
            }
#pragma unroll
            for (int mf = 0; mf < 4; ++mf) {
                const int cur = mf & 1;
                if (mf < 3) {
                    const uint32_t abn = sbase + (wm + (mf + 1) * 16) * SROWB
                                         + ga_off + ks * 32;
                    ldsm4(aa[cur ^ 1], abn);
                    ldsm4(aa[cur ^ 1] + 4, abn + 64);
                }
                const uint32_t* ah = aa[cur];
                const uint32_t* al = aa[cur] + 4;
#pragma unroll
                for (int nf = 0; nf < 4; ++nf)
                    mma_bf16(acc[mf][nf], ah, bh[nf >> 1] + (nf & 1) * 2);
#pragma unroll
                for (int nf = 0; nf < 4; ++nf)
                    mma_bf16(acc[mf][nf], ah, bl[nf >> 1] + (nf & 1) * 2);
#pragma unroll
                for (int nf = 0; nf < 4; ++nf)
                    mma_bf16(acc[mf][nf], al, bh[nf >> 1] + (nf & 1) * 2);
            }
        }
        if (c + 2 < 32) load_stage((c + 2) % 3, c + 2);
    }

#pragma unroll
    for (int mf = 0; mf < 4; ++mf) {
        const int r0 = bm + wm + mf * 16 + lr;
#pragma unroll
        for (int nf = 0; nf < 4; ++nf) {
            const int col = bn + wn + nf * 8 + lc * 2;
            *(float2*)(C + (size_t)r0 * Nstride + col) =
                make_float2(acc[mf][nf][0], acc[mf][nf][1]);
            *(float2*)(C + (size_t)(r0 + 8) * Nstride + col) =
                make_float2(acc[mf][nf][2], acc[mf][nf][3]);
        }
    }
}

// ---------------------------------------------------------------------------
// Fused RMSNorm + RoPE + head-major split (coalesced stores).
// ---------------------------------------------------------------------------
__global__ __launch_bounds__(256) void rmsrope_kernel(
    const float* __restrict__ qkv,
    const float* __restrict__ rope_cos, const float* __restrict__ rope_sin,
    const float* __restrict__ qw, const float* __restrict__ kw,
    __nv_bfloat16* __restrict__ qh, __nv_bfloat16* __restrict__ ql,
    __nv_bfloat16* __restrict__ kh, __nv_bfloat16* __restrict__ kl,
    __nv_bfloat16* __restrict__ vh, __nv_bfloat16* __restrict__ vl)
{
    const int t = blockIdx.x;
    const int warp = threadIdx.x >> 5, lane = threadIdx.x & 31;
    const int bb = t >> 10, ss = t & 1023;
    const float c1 = rope_cos[(size_t)t * HD + lane];
    const float c2 = rope_cos[(size_t)t * HD + 32 + lane];
    const float s1 = rope_sin[(size_t)t * HD + lane];
    const float s2 = rope_sin[(size_t)t * HD + 32 + lane];
    const float qscale = 0.125f * 1.4426950408889634f;
    const int m2 = (lane & 15) * 2;
    const bool hiHalf = lane >= 16;

    auto store_pair = [&](float r1, float r2, __nv_bfloat16* dh,
                          __nv_bfloat16* dl, size_t dst) {
        const float a1 = __shfl_sync(0xffffffffu, r1, m2);
        const float b1 = __shfl_sync(0xffffffffu, r1, m2 + 1);
        const float a2 = __shfl_sync(0xffffffffu, r2, m2);
        const float b2 = __shfl_sync(0xffffffffu, r2, m2 + 1);
        const float a = hiHalf ? a2 : a1;
        const float b = hiHalf ? b2 : b1;
        const float ha = bfhi(a), hb = bfhi(b);
        ((uint32_t*)(dh + dst))[lane] = packbf(ha, hb);
        ((uint32_t*)(dl + dst))[lane] = packbf(a - ha, b - hb);
    };

#pragma unroll
    for (int hh = 0; hh < 2; ++hh) {
        const int h = warp * 2 + hh;
        const size_t dst = ((size_t)(bb * HEADS + h) * SEQ + ss) * HD;
#pragma unroll
        for (int qk = 0; qk < 2; ++qk) {
            const float* p = qkv + (size_t)t * QKV_COLS + qk * DIM + h * HD;
            float x1 = p[lane], x2 = p[lane + 32];
            float sq = x1 * x1 + x2 * x2;
#pragma unroll
            for (int off = 16; off; off >>= 1)
                sq += __shfl_xor_sync(0xffffffffu, sq, off);
            const float r = rsqrtf(sq * (1.f / 64.f) + EPSF);
            const float* w = qk ? kw : qw;
            const float n1 = x1 * r * w[lane];
            const float n2 = x2 * r * w[lane + 32];
            float r1 = n1 * c1 - n2 * s1;
            float r2 = n2 * c2 + n1 * s2;
            if (qk == 0) { r1 *= qscale; r2 *= qscale; }
            store_pair(r1, r2, qk ? kh : qh, qk ? kl : ql, dst);
        }
        const float* pv = qkv + (size_t)t * QKV_COLS + 2 * DIM + h * HD;
        store_pair(pv[lane], pv[lane + 32], vh, vl, dst);
    }
}

// ===========================================================================
// Flash attention — EXACT R13 structure (measured best): 128-key blocks,
// 3-stage ring, single barrier per block, tail-load after compute.
// ===========================================================================
#define KROWB 272
#define KTILE 34816                      // 128 rows * 272
#define KSTG  69632                      // K + V
#define ATT_SMEM (3 * KSTG)              // 208896

__global__ __launch_bounds__(256, 1) void attn_kernel(
    const __nv_bfloat16* __restrict__ qh, const __nv_bfloat16* __restrict__ ql,
    const __nv_bfloat16* __restrict__ kh, const __nv_bfloat16* __restrict__ kl,
    const __nv_bfloat16* __restrict__ vh, const __nv_bfloat16* __restrict__ vl,
    __nv_bfloat16* __restrict__ ohi, __nv_bfloat16* __restrict__ olo)
{
    extern __shared__ char sma[];
    const uint32_t sb = smem_u32(sma);
    const int tid = threadIdx.x, wid = tid >> 5, lane = tid & 31;
    const int lr = lane >> 2, lc = lane & 3;
    const int h = blockIdx.y, b = blockIdx.z;
    const int q0 = blockIdx.x * 128;
    const int wq = wid * 16;
    const size_t hb = (size_t)(b * HEADS + h) * SEQ * HD;

    // --- Q tile load (into stage-0 region; extracted before load_kv(0)) ---
#pragma unroll
    for (int i = 0; i < 8; ++i) {
        const int slot = tid + i * 256;
        const int row = slot >> 4, c = slot & 15;
        const __nv_bfloat16* src = (c < 8 ? qh : ql) + hb + (size_t)(q0 + row) * HD + (c & 7) * 8;
        cpa16(sb + row * KROWB + c * 16, src);
    }
    asm volatile("cp.async.commit_group;" ::: "memory");
    asm volatile("cp.async.wait_group 0;" ::: "memory");
    __syncthreads();

    const uint32_t a_off =
        (uint32_t)((lane & 7) + ((lane >> 3) & 1) * 8) * KROWB + ((lane >> 4) & 1) * 16;
    const uint32_t b_off =
        (uint32_t)((lane & 7) + ((lane >> 4) & 1) * 8) * KROWB + ((lane >> 3) & 1) * 16;
    const uint32_t v_off =
        (uint32_t)(lane & 15) * KROWB + ((lane >> 4) & 1) * 16;
    uint32_t qfh[4][4], qfl[4][4];
#pragma unroll
    for (int ks = 0; ks < 4; ++ks) {
        ldsm4(qfh[ks], sb + wq * KROWB + a_off + ks * 32);
        ldsm4(qfl[ks], sb + wq * KROWB + a_off + ks * 32 + 128);
    }
    __syncthreads();   // Q region free for K/V stages

    auto load_kv = [&](int kb, int s) {
        const uint32_t kst = sb + s * KSTG;
#pragma unroll
        for (int i = 0; i < 8; ++i) {
            const int slot = tid + i * 256;
            const int row = slot >> 4, c = slot & 15;
            const size_t g = hb + (size_t)(kb * 128 + row) * HD + (c & 7) * 8;
            cpa16(kst + row * KROWB + c * 16, (c < 8 ? kh : kl) + g);
        }
#pragma unroll
        for (int i = 0; i < 8; ++i) {
            const int slot = tid + i * 256;
            const int row = slot >> 4, c = slot & 15;
            const size_t g = hb + (size_t)(kb * 128 + row) * HD + (c & 7) * 8;
            cpa16(kst + KTILE + row * KROWB + c * 16, (c < 8 ? vh : vl) + g);
        }
        asm volatile("cp.async.commit_group;" ::: "memory");
    };

    load_kv(0, 0);
    load_kv(1, 1);

    float m0 = -1e30f, m1 = -1e30f, l0 = 0.f, l1 = 0.f;
    float o[8][4];
#pragma unroll
    for (int nf = 0; nf < 8; ++nf)
#pragma unroll
        for (int r = 0; r < 4; ++r) o[nf][r] = 0.f;

    for (int kb = 0; kb < 8; ++kb) {
        const uint32_t kbase = sb + (kb % 3) * KSTG;
        const uint32_t vbase = kbase + KTILE;
        if (kb < 7) { asm volatile("cp.async.wait_group 1;" ::: "memory"); }
        else        { asm volatile("cp.async.wait_group 0;" ::: "memory"); }
        __syncthreads();   // stage kb visible; stage (kb-1)%3 free

        // --- S = Q K^T (3-term), 128 keys ---
        float s[16][4];
#pragma unroll
        for (int nf = 0; nf < 16; ++nf)
#pragma unroll
            for (int r = 0; r < 4; ++r) s[nf][r] = 0.f;

#pragma unroll
        for (int it = 0; it < 32; ++it) {
            const int ks = it >> 3, np = it & 7;
            uint32_t bh[4], bl[4];
            const uint32_t ba = kbase + np * 16 * KROWB + b_off + ks * 32;
            ldsm4(bh, ba);
            ldsm4(bl, ba + 128);
            mma_bf16(s[2 * np],     qfh[ks], bh);
            mma_bf16(s[2 * np + 1], qfh[ks], bh + 2);
            mma_bf16(s[2 * np],     qfh[ks], bl);
            mma_bf16(s[2 * np + 1], qfh[ks], bl + 2);
            mma_bf16(s[2 * np],     qfl[ks], bh);
            mma_bf16(s[2 * np + 1], qfl[ks], bh + 2);
        }

        // --- online softmax (rows lr, lr+8) ---
        float mx0 = -1e30f, mx1 = -1e30f;
#pragma unroll
        for (int nf = 0; nf < 16; ++nf) {
            mx0 = fmaxf(mx0, fmaxf(s[nf][0], s[nf][1]));
            mx1 = fmaxf(mx1, fmaxf(s[nf][2], s[nf][3]));
        }
        mx0 = fmaxf(mx0, __shfl_xor_sync(0xffffffffu, mx0, 1));
        mx0 = fmaxf(mx0, __shfl_xor_sync(0xffffffffu, mx0, 2));
        mx1 = fmaxf(mx1, __shfl_xor_sync(0xffffffffu, mx1, 1));
        mx1 = fmaxf(mx1, __shfl_xor_sync(0xffffffffu, mx1, 2));
        const float nm0 = fmaxf(m0, mx0), nm1 = fmaxf(m1, mx1);
        const float cr0 = ex2(m0 - nm0), cr1 = ex2(m1 - nm1);
        m0 = nm0; m1 = nm1;
        float sum0 = 0.f, sum1 = 0.f;
#pragma unroll
        for (int nf = 0; nf < 16; ++nf) {
            s[nf][0] = ex2(s[nf][0] - nm0); sum0 += s[nf][0];
            s[nf][1] = ex2(s[nf][1] - nm0); sum0 += s[nf][1];
            s[nf][2] = ex2(s[nf][2] - nm1); sum1 += s[nf][2];
            s[nf][3] = ex2(s[nf][3] - nm1); sum1 += s[nf][3];
        }
        sum0 += __shfl_xor_sync(0xffffffffu, sum0, 1);
        sum0 += __shfl_xor_sync(0xffffffffu, sum0, 2);
        sum1 += __shfl_xor_sync(0xffffffffu, sum1, 1);
        sum1 += __shfl_xor_sync(0xffffffffu, sum1, 2);
        l0 = l0 * cr0 + sum0;
        l1 = l1 * cr1 + sum1;
#pragma unroll
        for (int nf = 0; nf < 8; ++nf) {
            o[nf][0] *= cr0; o[nf][1] *= cr0;
            o[nf][2] *= cr1; o[nf][3] *= cr1;
        }

        // --- pack P hi/lo (8 k-steps of 16 keys) ---
        uint32_t ph[8][4], pl[8][4];
#pragma unroll
        for (int ks = 0; ks < 8; ++ks) {
            const float p00 = s[2 * ks][0],     p01 = s[2 * ks][1];
            const float p10 = s[2 * ks][2],     p11 = s[2 * ks][3];
            const float p20 = s[2 * ks + 1][0], p21 = s[2 * ks + 1][1];
            const float p30 = s[2 * ks + 1][2], p31 = s[2 * ks + 1][3];
            const float h00 = bfhi(p00), h01 = bfhi(p01);
            const float h10 = bfhi(p10), h11 = bfhi(p11);
            const float h20 = bfhi(p20), h21 = bfhi(p21);
            const float h30 = bfhi(p30), h31 = bfhi(p31);
            ph[ks][0] = packbf(h00, h01); pl[ks][0] = packbf(p00 - h00, p01 - h01);
            ph[ks][1] = packbf(h10, h11); pl[ks][1] = packbf(p10 - h10, p11 - h11);
            ph[ks][2] = packbf(h20, h21); pl[ks][2] = packbf(p20 - h20, p21 - h21);
            ph[ks][3] = packbf(h30, h31); pl[ks][3] = packbf(p30 - h30, p31 - h31);
        }

        // --- O += P V (3-term) ---
#pragma unroll
        for (int it = 0; it < 32; ++it) {
            const int ks = it >> 2, ng = it & 3;
            uint32_t vfh[4], vfl[4];
            const uint32_t va = vbase + ks * 16 * KROWB + v_off + ng * 32;
            ldsm4t(vfh, va);
            ldsm4t(vfl, va + 128);
            mma_bf16(o[2 * ng],     ph[ks], vfh);
            mma_bf16(o[2 * ng + 1], ph[ks], vfh + 2);
            mma_bf16(o[2 * ng],     ph[ks], vfl);
            mma_bf16(o[2 * ng + 1], ph[ks], vfl + 2);
            mma_bf16(o[2 * ng],     pl[ks], vfh);
            mma_bf16(o[2 * ng + 1], pl[ks], vfh + 2);
        }

        // tail-load AFTER compute (R11-proven ordering)
        if (kb + 2 < 8) load_kv(kb + 2, (kb + 2) % 3);
    }

    // --- epilogue ---
    const float i0 = 1.f / l0, i1 = 1.f / l1;
    const int t0 = b * SEQ + q0 + wq + lr;
#pragma unroll
    for (int nf = 0; nf < 8; ++nf) {
        const int col = h * HD + nf * 8 + lc * 2;
        const float v0 = o[nf][0] * i0, v1 = o[nf][1] * i0;
        const float h0 = bfhi(v0), h1 = bfhi(v1);
        ((uint32_t*)ohi)[((size_t)t0 * DIM + col) >> 1] = packbf(h0, h1);
        ((uint32_t*)olo)[((size_t)t0 * DIM + col) >> 1] = packbf(v0 - h0, v1 - h1);
        const float v2 = o[nf][2] * i1, v3 = o[nf][3] * i1;
        const float h2 = bfhi(v2), h3 = bfhi(v3);
        ((uint32_t*)ohi)[((size_t)(t0 + 8) * DIM + col) >> 1] = packbf(h2, h3);
        ((uint32_t*)olo)[((size_t)(t0 + 8) * DIM + col) >> 1] = packbf(v2 - h2, v3 - h3);
    }
}

// ---------------------------------------------------------------------------
extern "C" void kernel_launch(void* const* d_in, const int* in_sizes, int n_in,
                              void* d_out, int out_size)
{
    const float *x = 0, *rc = 0, *rs = 0, *wqkv = 0, *wproj = 0, *qw = 0, *kw = 0;
    for (int i = 0; i < n_in; ++i) {
        const int s = in_sizes[i];
        if (s == T_TOK * DIM && !x)            x = (const float*)d_in[i];
        else if (s == T_TOK * HD)              { if (!rc) rc = (const float*)d_in[i];
                                                 else if (!rs) rs = (const float*)d_in[i]; }
        else if (s == QKV_COLS * DIM)          wqkv = (const float*)d_in[i];
        else if (s == DIM * DIM && !wproj)     wproj = (const float*)d_in[i];
        else if (s == HD)                      { if (!qw) qw = (const float*)d_in[i];
                                                 else if (!kw) kw = (const float*)d_in[i]; }
    }
    float* out = (float*)d_out;

    void *pqkv, *pxh, *pxl, *pwqh, *pwql, *pwph, *pwpl, *pah, *pal;
    void *pqh, *pql, *pkh, *pkl, *pvh, *pvl;
    cudaGetSymbolAddress(&pqkv, g_qkv);
    cudaGetSymbolAddress(&pxh, g_xhi);  cudaGetSymbolAddress(&pxl, g_xlo);
    cudaGetSymbolAddress(&pwqh, g_wqhi); cudaGetSymbolAddress(&pwql, g_wqlo);
    cudaGetSymbolAddress(&pwph, g_wphi); cudaGetSymbolAddress(&pwpl, g_wplo);
    cudaGetSymbolAddress(&pah, g_ahi);  cudaGetSymbolAddress(&pal, g_alo);
    cudaGetSymbolAddress(&pqh, g_qh);   cudaGetSymbolAddress(&pql, g_ql);
    cudaGetSymbolAddress(&pkh, g_kh);   cudaGetSymbolAddress(&pkl, g_kl);
    cudaGetSymbolAddress(&pvh, g_vh);   cudaGetSymbolAddress(&pvl, g_vl);

    cudaFuncSetAttribute(gemm_split_kernel,
                         cudaFuncAttributeMaxDynamicSharedMemorySize, GSMEM);
    cudaFuncSetAttribute(attn_kernel,
                         cudaFuncAttributeMaxDynamicSharedMemorySize, ATT_SMEM);

    // 0) fp32 -> (hi,lo) bf16 splits (single merged launch)
    split_all_kernel<<<(N4_TOT + 255) / 256, 256>>>(
        x, wqkv, wproj,
        (__nv_bfloat16*)pxh, (__nv_bfloat16*)pxl,
        (__nv_bfloat16*)pwqh, (__nv_bfloat16*)pwql,
        (__nv_bfloat16*)pwph, (__nv_bfloat16*)pwpl);

    // 1) QKV = x @ w_qkv^T
    gemm_split_kernel<<<dim3(QKV_COLS / 128, T_TOK / 128), 256, GSMEM>>>(
        (__nv_bfloat16*)pxh, (__nv_bfloat16*)pxl,
        (__nv_bfloat16*)pwqh, (__nv_bfloat16*)pwql, (float*)pqkv, QKV_COLS);
    // 2) RMSNorm + RoPE + split q,k,v to head-major bf16
    rmsrope_kernel<<<T_TOK, 256>>>(
        (const float*)pqkv, rc, rs, qw, kw,
        (__nv_bfloat16*)pqh, (__nv_bfloat16*)pql,
        (__nv_bfloat16*)pkh, (__nv_bfloat16*)pkl,
        (__nv_bfloat16*)pvh, (__nv_bfloat16*)pvl);
    // 3) Attention
    attn_kernel<<<dim3(SEQ / 128, HEADS, BATCH), 256, ATT_SMEM>>>(
        (__nv_bfloat16*)pqh, (__nv_bfloat16*)pql,
        (__nv_bfloat16*)pkh, (__nv_bfloat16*)pkl,
        (__nv_bfloat16*)pvh, (__nv_bfloat16*)pvl,
        (__nv_bfloat16*)pah, (__nv_bfloat16*)pal);
    // 4) out = attn @ w_proj^T
    gemm_split_kernel<<<dim3(DIM / 128, T_TOK / 128), 256, GSMEM>>>(
        (__nv_bfloat16*)pah, (__nv_bfloat16*)pal,
        (__nv_bfloat16*)pwph, (__nv_bfloat16*)pwpl, out, DIM);
}